// round 1
// baseline (speedup 1.0000x reference)
#include <cuda_runtime.h>
#include <math.h>
#include <stddef.h>

// Problem constants (fixed by setup_inputs)
#define Bq   32
#define Sq   2048
#define Hq   512
#define Eq   256
#define Tq   32
#define NLq  2000
#define CATq 1280           // [h_t(512), weighted(512), x(256)]
#define PSTRIDE 516         // per-partial: m, Z, pad, pad, w[512]

// ---------------- scratch (static device globals; no allocations) ------------
__device__ float g_ctx[(size_t)Bq * Sq * Hq];   // 128 MB projected context [b][s][h]
__device__ float g_h[Bq * Hq];
__device__ float g_c[Bq * Hq];
__device__ float g_hlstm[Bq * Hq];
__device__ float g_inp[Bq * Hq];
__device__ float g_part[(size_t)Bq * 32 * PSTRIDE];  // attention split partials
__device__ float g_cat[(size_t)Bq * Tq * CATq];      // rows r = b*T + t

// ---------------- math helpers ----------------------------------------------
__device__ __forceinline__ float fast_tanh(float x) {
    // (e^{2x}-1)/(e^{2x}+1), clamped; abs err ~1e-7
    x = fminf(fmaxf(x, -15.f), 15.f);
    float e = __expf(2.f * x);
    return __fdividef(e - 1.f, e + 1.f);
}
__device__ __forceinline__ float sigmoidf_(float x) {
    return __fdividef(1.f, 1.f + __expf(-x));
}

// ---------------- init: h0/c0 copy + gather all step inputs x_t --------------
__global__ void k_init(const float* __restrict__ h0, const float* __restrict__ c0,
                       const float* __restrict__ dec_in, const int* __restrict__ labels,
                       const float* __restrict__ lemb) {
    int i = blockIdx.x * blockDim.x + threadIdx.x;
    if (i < Bq * Hq) { g_h[i] = h0[i]; g_c[i] = c0[i]; }
    int stride = gridDim.x * blockDim.x;
    for (int j = i; j < Bq * Tq * Eq; j += stride) {
        int e = j % Eq;
        int t = (j / Eq) % Tq;
        int b = j / (Eq * Tq);
        float v;
        if (t == 0) v = dec_in[b * Eq + e];
        else {
            int lab = labels[b * Tq + (t - 1)];
            v = lemb[(size_t)lab * Eq + e];
        }
        g_cat[((size_t)b * Tq + t) * CATq + 1024 + e] = v;
    }
}

// ---------------- prologue SGEMM: ctx = context @ W_ctx^T + b_ctx ------------
// M=65536, N=512, K=512. BM=128, BN=64, BK=16, 256 threads, 8x4 per thread.
__global__ void k_sgemm_ctx(const float* __restrict__ A, const float* __restrict__ W,
                            const float* __restrict__ bias) {
    __shared__ float As[16][128];
    __shared__ float Ws[16][64];
    const int tid  = threadIdx.x;
    const int m0   = blockIdx.x * 128;
    const int n0   = blockIdx.y * 64;
    const int arow = tid >> 1;            // 0..127
    const int acol = (tid & 1) * 8;       // 0 or 8
    const int brow = tid >> 2;            // 0..63
    const int bcol = (tid & 3) * 4;
    const int ty   = tid >> 4;            // 0..15 -> rows ty*8..+7
    const int tx   = tid & 15;            // cols tx*4..+3

    float acc[8][4];
#pragma unroll
    for (int i = 0; i < 8; i++)
#pragma unroll
        for (int j = 0; j < 4; j++) acc[i][j] = 0.f;

    for (int k0 = 0; k0 < 512; k0 += 16) {
        float4 a0 = *(const float4*)(A + (size_t)(m0 + arow) * 512 + k0 + acol);
        float4 a1 = *(const float4*)(A + (size_t)(m0 + arow) * 512 + k0 + acol + 4);
        float4 bv = *(const float4*)(W + (size_t)(n0 + brow) * 512 + k0 + bcol);
        __syncthreads();
        As[acol + 0][arow] = a0.x; As[acol + 1][arow] = a0.y;
        As[acol + 2][arow] = a0.z; As[acol + 3][arow] = a0.w;
        As[acol + 4][arow] = a1.x; As[acol + 5][arow] = a1.y;
        As[acol + 6][arow] = a1.z; As[acol + 7][arow] = a1.w;
        Ws[bcol + 0][brow] = bv.x; Ws[bcol + 1][brow] = bv.y;
        Ws[bcol + 2][brow] = bv.z; Ws[bcol + 3][brow] = bv.w;
        __syncthreads();
#pragma unroll
        for (int k = 0; k < 16; k++) {
            float4 b4  = *(const float4*)&Ws[k][tx * 4];
            float4 ar0 = *(const float4*)&As[k][ty * 8];
            float4 ar1 = *(const float4*)&As[k][ty * 8 + 4];
            float ar[8] = {ar0.x, ar0.y, ar0.z, ar0.w, ar1.x, ar1.y, ar1.z, ar1.w};
#pragma unroll
            for (int i = 0; i < 8; i++) {
                acc[i][0] += ar[i] * b4.x;
                acc[i][1] += ar[i] * b4.y;
                acc[i][2] += ar[i] * b4.z;
                acc[i][3] += ar[i] * b4.w;
            }
        }
    }
    float4 bb = *(const float4*)(bias + n0 + tx * 4);
#pragma unroll
    for (int i = 0; i < 8; i++) {
        float4 r;
        r.x = acc[i][0] + bb.x; r.y = acc[i][1] + bb.y;
        r.z = acc[i][2] + bb.z; r.w = acc[i][3] + bb.w;
        *(float4*)(g_ctx + (size_t)(m0 + ty * 8 + i) * 512 + n0 + tx * 4) = r;
    }
}

// ---------------- per-step: gates + LSTM pointwise ---------------------------
// warp = one h-slot j (0..511), lanes = batch b (0..31)
__global__ void k_gates(const float* __restrict__ Wih, const float* __restrict__ bih,
                        const float* __restrict__ Whh, const float* __restrict__ bhh,
                        int t) {
    int j = blockIdx.x * 4 + (threadIdx.x >> 5);
    int b = threadIdx.x & 31;
    const float* xrow = g_cat + ((size_t)b * Tq + t) * CATq + 1024;
    const float* hrow = g_h + b * Hq;
    const float* w0 = Wih + (size_t)j * Eq;
    const float* w1 = Wih + (size_t)(j + 512) * Eq;
    const float* w2 = Wih + (size_t)(j + 1024) * Eq;
    const float* w3 = Wih + (size_t)(j + 1536) * Eq;
    float s0 = 0.f, s1 = 0.f, s2 = 0.f, s3 = 0.f;
#pragma unroll 4
    for (int e = 0; e < Eq; e += 4) {
        float4 xv = *(const float4*)(xrow + e);
        float4 a = *(const float4*)(w0 + e);
        float4 c = *(const float4*)(w1 + e);
        float4 d = *(const float4*)(w2 + e);
        float4 f = *(const float4*)(w3 + e);
        s0 += xv.x * a.x + xv.y * a.y + xv.z * a.z + xv.w * a.w;
        s1 += xv.x * c.x + xv.y * c.y + xv.z * c.z + xv.w * c.w;
        s2 += xv.x * d.x + xv.y * d.y + xv.z * d.z + xv.w * d.w;
        s3 += xv.x * f.x + xv.y * f.y + xv.z * f.z + xv.w * f.w;
    }
    const float* u0 = Whh + (size_t)j * Hq;
    const float* u1 = Whh + (size_t)(j + 512) * Hq;
    const float* u2 = Whh + (size_t)(j + 1024) * Hq;
    const float* u3 = Whh + (size_t)(j + 1536) * Hq;
#pragma unroll 4
    for (int k = 0; k < Hq; k += 4) {
        float4 hv = *(const float4*)(hrow + k);
        float4 a = *(const float4*)(u0 + k);
        float4 c = *(const float4*)(u1 + k);
        float4 d = *(const float4*)(u2 + k);
        float4 f = *(const float4*)(u3 + k);
        s0 += hv.x * a.x + hv.y * a.y + hv.z * a.z + hv.w * a.w;
        s1 += hv.x * c.x + hv.y * c.y + hv.z * c.z + hv.w * c.w;
        s2 += hv.x * d.x + hv.y * d.y + hv.z * d.z + hv.w * d.w;
        s3 += hv.x * f.x + hv.y * f.y + hv.z * f.z + hv.w * f.w;
    }
    s0 += bih[j]        + bhh[j];
    s1 += bih[j + 512]  + bhh[j + 512];
    s2 += bih[j + 1024] + bhh[j + 1024];
    s3 += bih[j + 1536] + bhh[j + 1536];
    float ig = sigmoidf_(s0), fg = sigmoidf_(s1);
    float gg = fast_tanh(s2), og = sigmoidf_(s3);
    float cp = g_c[b * Hq + j];
    float ct = fg * cp + ig * gg;
    float hl = og * fast_tanh(ct);
    g_c[b * Hq + j]     = ct;
    g_hlstm[b * Hq + j] = hl;
}

// ---------------- per-step: inp = h_lstm @ W_in^T + b_in ---------------------
__global__ void k_inp(const float* __restrict__ Win, const float* __restrict__ bin) {
    int j = blockIdx.x * 4 + (threadIdx.x >> 5);
    int b = threadIdx.x & 31;
    const float* hl = g_hlstm + b * Hq;
    const float* wr = Win + (size_t)j * Hq;
    float s = bin[j];
#pragma unroll 4
    for (int k = 0; k < Hq; k += 4) {
        float4 hv = *(const float4*)(hl + k);
        float4 wv = *(const float4*)(wr + k);
        s += hv.x * wv.x + hv.y * wv.y + hv.z * wv.z + hv.w * wv.w;
    }
    g_inp[b * Hq + j] = s;
}

// ---------------- per-step: fused attention (single pass over ctx) -----------
// grid (4, B); 8 warps/block; warp p handles s in [p*64, p*64+64).
// Online softmax + running weighted-context vector held in registers.
__global__ void k_attn(const float* __restrict__ V) {
    int b = blockIdx.y;
    int p = blockIdx.x * 8 + (threadIdx.x >> 5);
    int l = threadIdx.x & 31;

    float4 v0 = *(const float4*)(V + 4 * l);
    float4 v1 = *(const float4*)(V + 128 + 4 * l);
    float4 v2 = *(const float4*)(V + 256 + 4 * l);
    float4 v3 = *(const float4*)(V + 384 + 4 * l);
    const float* ip = g_inp + b * Hq;
    float4 i0 = *(const float4*)(ip + 4 * l);
    float4 i1 = *(const float4*)(ip + 128 + 4 * l);
    float4 i2 = *(const float4*)(ip + 256 + 4 * l);
    float4 i3 = *(const float4*)(ip + 384 + 4 * l);

    float4 w0 = {0, 0, 0, 0}, w1 = {0, 0, 0, 0}, w2 = {0, 0, 0, 0}, w3 = {0, 0, 0, 0};
    float m = -1e30f, Z = 0.f;

    const float* base = g_ctx + ((size_t)b * Sq + (size_t)p * 64) * Hq;
    for (int s = 0; s < 64; ++s, base += Hq) {
        float4 c0 = *(const float4*)(base + 4 * l);
        float4 c1 = *(const float4*)(base + 128 + 4 * l);
        float4 c2 = *(const float4*)(base + 256 + 4 * l);
        float4 c3 = *(const float4*)(base + 384 + 4 * l);
        float part;
        part  = v0.x * fast_tanh(i0.x + c0.x);
        part += v0.y * fast_tanh(i0.y + c0.y);
        part += v0.z * fast_tanh(i0.z + c0.z);
        part += v0.w * fast_tanh(i0.w + c0.w);
        part += v1.x * fast_tanh(i1.x + c1.x);
        part += v1.y * fast_tanh(i1.y + c1.y);
        part += v1.z * fast_tanh(i1.z + c1.z);
        part += v1.w * fast_tanh(i1.w + c1.w);
        part += v2.x * fast_tanh(i2.x + c2.x);
        part += v2.y * fast_tanh(i2.y + c2.y);
        part += v2.z * fast_tanh(i2.z + c2.z);
        part += v2.w * fast_tanh(i2.w + c2.w);
        part += v3.x * fast_tanh(i3.x + c3.x);
        part += v3.y * fast_tanh(i3.y + c3.y);
        part += v3.z * fast_tanh(i3.z + c3.z);
        part += v3.w * fast_tanh(i3.w + c3.w);
#pragma unroll
        for (int off = 16; off; off >>= 1)
            part += __shfl_xor_sync(0xffffffffu, part, off);

        float nm   = fmaxf(m, part);
        float corr = __expf(m - nm);     // m = -1e30 first iter -> corr = 0
        float pe   = __expf(part - nm);
        Z = Z * corr + pe;
        w0.x = w0.x * corr + pe * c0.x; w0.y = w0.y * corr + pe * c0.y;
        w0.z = w0.z * corr + pe * c0.z; w0.w = w0.w * corr + pe * c0.w;
        w1.x = w1.x * corr + pe * c1.x; w1.y = w1.y * corr + pe * c1.y;
        w1.z = w1.z * corr + pe * c1.z; w1.w = w1.w * corr + pe * c1.w;
        w2.x = w2.x * corr + pe * c2.x; w2.y = w2.y * corr + pe * c2.y;
        w2.z = w2.z * corr + pe * c2.z; w2.w = w2.w * corr + pe * c2.w;
        w3.x = w3.x * corr + pe * c3.x; w3.y = w3.y * corr + pe * c3.y;
        w3.z = w3.z * corr + pe * c3.z; w3.w = w3.w * corr + pe * c3.w;
        m = nm;
    }
    float* pp = g_part + ((size_t)b * 32 + p) * PSTRIDE;
    if (l == 0) { pp[0] = m; pp[1] = Z; }
    *(float4*)(pp + 4 + 4 * l)       = w0;
    *(float4*)(pp + 4 + 128 + 4 * l) = w1;
    *(float4*)(pp + 4 + 256 + 4 * l) = w2;
    *(float4*)(pp + 4 + 384 + 4 * l) = w3;
}

// ---------------- per-step: combine partials + h_t GEMM ----------------------
// block = one b, 512 threads = one h each.
__global__ void k_combine(const float* __restrict__ Who, const float* __restrict__ bho,
                          int t, float* __restrict__ out_hf) {
    int b = blockIdx.x;
    int h = threadIdx.x;
    __shared__ float sm[32], sz[32], wsm[512];
    if (h < 32) {
        const float* pp = g_part + ((size_t)b * 32 + h) * PSTRIDE;
        sm[h] = pp[0]; sz[h] = pp[1];
    }
    __syncthreads();
    float M = -1e30f;
#pragma unroll
    for (int p2 = 0; p2 < 32; p2++) M = fmaxf(M, sm[p2]);
    float Zt = 0.f, wnum = 0.f;
#pragma unroll
    for (int p2 = 0; p2 < 32; p2++) {
        float e = __expf(sm[p2] - M);
        Zt   += e * sz[p2];
        wnum += e * g_part[((size_t)b * 32 + p2) * PSTRIDE + 4 + h];
    }
    float wgt = wnum / Zt;
    wsm[h] = wgt;
    float* catrow = g_cat + ((size_t)b * Tq + t) * CATq;
    catrow[512 + h] = wgt;
    __syncthreads();

    float acc = bho[h];
    const float* wr = Who + (size_t)h * 1024;
    const float* hl = g_hlstm + b * Hq;
#pragma unroll 4
    for (int k = 0; k < 512; k += 4) {
        float4 wv = *(const float4*)(wr + k);
        acc += wsm[k] * wv.x + wsm[k + 1] * wv.y + wsm[k + 2] * wv.z + wsm[k + 3] * wv.w;
    }
#pragma unroll 4
    for (int k = 0; k < 512; k += 4) {
        float4 wv = *(const float4*)(wr + 512 + k);
        float4 hv = *(const float4*)(hl + k);
        acc += hv.x * wv.x + hv.y * wv.y + hv.z * wv.z + hv.w * wv.w;
    }
    float ht = fast_tanh(acc);
    g_h[b * Hq + h] = ht;
    catrow[h] = ht;
    if (t == Tq - 1) out_hf[b * Hq + h] = ht;
}

// ---------------- epilogue SGEMM: logits = cat @ W_out^T + b_out -------------
// M=1024, N=2000 (padded to 2048), K=1280. Same tiling as prologue, with guards.
__global__ void k_sgemm_out(const float* __restrict__ Wout, const float* __restrict__ bout,
                            float* __restrict__ C) {
    __shared__ float As[16][128];
    __shared__ float Ws[16][64];
    const int tid  = threadIdx.x;
    const int m0   = blockIdx.x * 128;
    const int n0   = blockIdx.y * 64;
    const int arow = tid >> 1;
    const int acol = (tid & 1) * 8;
    const int brow = tid >> 2;
    const int bcol = (tid & 3) * 4;
    const int ty   = tid >> 4;
    const int tx   = tid & 15;

    float acc[8][4];
#pragma unroll
    for (int i = 0; i < 8; i++)
#pragma unroll
        for (int j = 0; j < 4; j++) acc[i][j] = 0.f;

    const bool wok = (n0 + brow) < NLq;
    for (int k0 = 0; k0 < CATq; k0 += 16) {
        float4 a0 = *(const float4*)(g_cat + (size_t)(m0 + arow) * CATq + k0 + acol);
        float4 a1 = *(const float4*)(g_cat + (size_t)(m0 + arow) * CATq + k0 + acol + 4);
        float4 bv = {0, 0, 0, 0};
        if (wok) bv = *(const float4*)(Wout + (size_t)(n0 + brow) * CATq + k0 + bcol);
        __syncthreads();
        As[acol + 0][arow] = a0.x; As[acol + 1][arow] = a0.y;
        As[acol + 2][arow] = a0.z; As[acol + 3][arow] = a0.w;
        As[acol + 4][arow] = a1.x; As[acol + 5][arow] = a1.y;
        As[acol + 6][arow] = a1.z; As[acol + 7][arow] = a1.w;
        Ws[bcol + 0][brow] = bv.x; Ws[bcol + 1][brow] = bv.y;
        Ws[bcol + 2][brow] = bv.z; Ws[bcol + 3][brow] = bv.w;
        __syncthreads();
#pragma unroll
        for (int k = 0; k < 16; k++) {
            float4 b4  = *(const float4*)&Ws[k][tx * 4];
            float4 ar0 = *(const float4*)&As[k][ty * 8];
            float4 ar1 = *(const float4*)&As[k][ty * 8 + 4];
            float ar[8] = {ar0.x, ar0.y, ar0.z, ar0.w, ar1.x, ar1.y, ar1.z, ar1.w};
#pragma unroll
            for (int i = 0; i < 8; i++) {
                acc[i][0] += ar[i] * b4.x;
                acc[i][1] += ar[i] * b4.y;
                acc[i][2] += ar[i] * b4.z;
                acc[i][3] += ar[i] * b4.w;
            }
        }
    }
#pragma unroll
    for (int i = 0; i < 8; i++) {
#pragma unroll
        for (int j = 0; j < 4; j++) {
            int n = n0 + tx * 4 + j;
            if (n < NLq)
                C[(size_t)(m0 + ty * 8 + i) * NLq + n] = acc[i][j] + bout[n];
        }
    }
}

// ---------------- epilogue: argmax -> preds (as float) -----------------------
__global__ void k_argmax(const float* __restrict__ logits, float* __restrict__ preds) {
    int r = blockIdx.x * (blockDim.x >> 5) + (threadIdx.x >> 5);   // 0..1023
    int lane = threadIdx.x & 31;
    const float* row = logits + (size_t)r * NLq;
    float bv = -1e30f; int bi = 0;
    for (int i = lane; i < NLq; i += 32) {
        float v = row[i];
        if (v > bv) { bv = v; bi = i; }
    }
#pragma unroll
    for (int off = 16; off; off >>= 1) {
        float ov = __shfl_xor_sync(0xffffffffu, bv, off);
        int   oi = __shfl_xor_sync(0xffffffffu, bi, off);
        if (ov > bv || (ov == bv && oi < bi)) { bv = ov; bi = oi; }
    }
    if (lane == 0) preds[r] = (float)bi;
}

__global__ void k_copy_cf(float* __restrict__ out_cf) {
    int i = blockIdx.x * blockDim.x + threadIdx.x;
    if (i < Bq * Hq) out_cf[i] = g_c[i];
}

// ---------------- launch -----------------------------------------------------
extern "C" void kernel_launch(void* const* d_in, const int* in_sizes, int n_in,
                              void* d_out, int out_size) {
    // metadata order: sent_lengths, output_length, decoder_input, h0, c0, context,
    // cur_labels, label_emb, W_ih, b_ih, W_hh, b_hh, W_in, b_in, W_ctx, b_ctx,
    // V, W_ho, b_ho, W_out, b_out
    const float* dec_in  = (const float*)d_in[2];
    const float* h0      = (const float*)d_in[3];
    const float* c0      = (const float*)d_in[4];
    const float* context = (const float*)d_in[5];
    const int*   labels  = (const int*)d_in[6];
    const float* lemb    = (const float*)d_in[7];
    const float* Wih     = (const float*)d_in[8];
    const float* bih     = (const float*)d_in[9];
    const float* Whh     = (const float*)d_in[10];
    const float* bhh     = (const float*)d_in[11];
    const float* Win     = (const float*)d_in[12];
    const float* bin     = (const float*)d_in[13];
    const float* Wctx    = (const float*)d_in[14];
    const float* bctx    = (const float*)d_in[15];
    const float* V       = (const float*)d_in[16];
    const float* Who     = (const float*)d_in[17];
    const float* bho     = (const float*)d_in[18];
    const float* Wout    = (const float*)d_in[19];
    const float* bout    = (const float*)d_in[20];

    float* out      = (float*)d_out;
    float* o_logits = out;                                  // B*T*NL = 2,048,000
    float* o_preds  = out + (size_t)Bq * Tq * NLq;          // + 1024
    float* o_hf     = o_preds + Bq * Tq;                    // + 16384
    float* o_cf     = o_hf + Bq * Hq;                       // + 16384

    k_init<<<256, 256>>>(h0, c0, dec_in, labels, lemb);
    k_sgemm_ctx<<<dim3(512, 8), 256>>>(context, Wctx, bctx);

    for (int t = 0; t < Tq; ++t) {
        k_gates<<<128, 128>>>(Wih, bih, Whh, bhh, t);
        k_inp<<<128, 128>>>(Win, bin);
        k_attn<<<dim3(4, Bq), 256>>>(V);
        k_combine<<<Bq, 512>>>(Who, bho, t, o_hf);
    }

    k_sgemm_out<<<dim3(8, 32), 256>>>(Wout, bout, o_logits);
    k_argmax<<<128, 256>>>(o_logits, o_preds);
    k_copy_cf<<<64, 256>>>(o_cf);
}

// round 2
// speedup vs baseline: 3.1080x; 3.1080x over previous
#include <cuda_runtime.h>
#include <math.h>
#include <stddef.h>

// Problem constants
#define Bq   32
#define Sq   2048
#define Hq   512
#define Eq   256
#define Tq   32
#define NLq  2000
#define CATq 1280           // [h_t(512), weighted(512), x(256)]
#define NPq  64             // attention partials per batch row
#define PSTRIDE 516         // per-partial: m, Z, pad, pad, w[512]

// ---------------- scratch ----------------------------------------------------
__device__ float g_ctx[(size_t)Bq * Sq * Hq];   // 128 MB projected context
__device__ float g_h[Bq * Hq];
__device__ float g_c[Bq * Hq];
__device__ float g_hlstm[Bq * Hq];
__device__ float g_inp[Bq * Hq];
__device__ float g_part[(size_t)Bq * NPq * PSTRIDE];
__device__ float g_cat[(size_t)Bq * Tq * CATq];

// ---------------- math -------------------------------------------------------
__device__ __forceinline__ float fast_tanh(float x) {     // accurate (~1e-7)
    x = fminf(fmaxf(x, -15.f), 15.f);
    float e = __expf(2.f * x);
    return __fdividef(e - 1.f, e + 1.f);
}
__device__ __forceinline__ float tanh_hw(float x) {       // MUFU.TANH (~1e-5)
    float y;
    asm("tanh.approx.f32 %0, %1;" : "=f"(y) : "f"(x));
    return y;
}
__device__ __forceinline__ float sigmoidf_(float x) {
    return __fdividef(1.f, 1.f + __expf(-x));
}
__device__ __forceinline__ float dot4(float4 a, float4 b) {
    return a.x * b.x + a.y * b.y + a.z * b.z + a.w * b.w;
}

// ---------------- init -------------------------------------------------------
__global__ void k_init(const float* __restrict__ h0, const float* __restrict__ c0,
                       const float* __restrict__ dec_in, const int* __restrict__ labels,
                       const float* __restrict__ lemb) {
    int i = blockIdx.x * blockDim.x + threadIdx.x;
    if (i < Bq * Hq) { g_h[i] = h0[i]; g_c[i] = c0[i]; }
    int stride = gridDim.x * blockDim.x;
    for (int j = i; j < Bq * Tq * Eq; j += stride) {
        int e = j % Eq;
        int t = (j / Eq) % Tq;
        int b = j / (Eq * Tq);
        float v;
        if (t == 0) v = dec_in[b * Eq + e];
        else {
            int lab = labels[b * Tq + (t - 1)];
            v = lemb[(size_t)lab * Eq + e];
        }
        g_cat[((size_t)b * Tq + t) * CATq + 1024 + e] = v;
    }
}

// ---------------- prologue SGEMM: ctx = context @ W_ctx^T + b_ctx ------------
// M=65536, N=512, K=512. BM=BN=128, BK=8, 256 thr, 8x8/thread, double buffer.
__global__ __launch_bounds__(256) void k_sgemm_ctx(const float* __restrict__ A,
                                                   const float* __restrict__ W,
                                                   const float* __restrict__ bias) {
    __shared__ float As[2][8][128];
    __shared__ float Ws[2][8][128];
    const int tid = threadIdx.x;
    const int m0  = blockIdx.x * 128;
    const int n0  = blockIdx.y * 128;
    const int lr  = tid >> 1;
    const int lc  = (tid & 1) * 4;
    const int ty  = tid >> 4;
    const int tx  = tid & 15;

    float acc[8][8];
#pragma unroll
    for (int i = 0; i < 8; i++)
#pragma unroll
        for (int j = 0; j < 8; j++) acc[i][j] = 0.f;

    float4 a = *(const float4*)(A + (size_t)(m0 + lr) * 512 + lc);
    float4 w = *(const float4*)(W + (size_t)(n0 + lr) * 512 + lc);
    As[0][lc + 0][lr] = a.x; As[0][lc + 1][lr] = a.y;
    As[0][lc + 2][lr] = a.z; As[0][lc + 3][lr] = a.w;
    Ws[0][lc + 0][lr] = w.x; Ws[0][lc + 1][lr] = w.y;
    Ws[0][lc + 2][lr] = w.z; Ws[0][lc + 3][lr] = w.w;
    __syncthreads();

    int buf = 0;
    for (int k0 = 8; k0 <= 512; k0 += 8) {
        if (k0 < 512) {
            a = *(const float4*)(A + (size_t)(m0 + lr) * 512 + k0 + lc);
            w = *(const float4*)(W + (size_t)(n0 + lr) * 512 + k0 + lc);
        }
#pragma unroll
        for (int k = 0; k < 8; k++) {
            float4 a0 = *(const float4*)&As[buf][k][ty * 8];
            float4 a1 = *(const float4*)&As[buf][k][ty * 8 + 4];
            float4 b0 = *(const float4*)&Ws[buf][k][tx * 8];
            float4 b1 = *(const float4*)&Ws[buf][k][tx * 8 + 4];
            float ar[8] = {a0.x, a0.y, a0.z, a0.w, a1.x, a1.y, a1.z, a1.w};
            float br[8] = {b0.x, b0.y, b0.z, b0.w, b1.x, b1.y, b1.z, b1.w};
#pragma unroll
            for (int i = 0; i < 8; i++)
#pragma unroll
                for (int j = 0; j < 8; j++) acc[i][j] += ar[i] * br[j];
        }
        if (k0 < 512) {
            buf ^= 1;
            As[buf][lc + 0][lr] = a.x; As[buf][lc + 1][lr] = a.y;
            As[buf][lc + 2][lr] = a.z; As[buf][lc + 3][lr] = a.w;
            Ws[buf][lc + 0][lr] = w.x; Ws[buf][lc + 1][lr] = w.y;
            Ws[buf][lc + 2][lr] = w.z; Ws[buf][lc + 3][lr] = w.w;
            __syncthreads();
        }
    }
    float4 bb0 = *(const float4*)(bias + n0 + tx * 8);
    float4 bb1 = *(const float4*)(bias + n0 + tx * 8 + 4);
#pragma unroll
    for (int i = 0; i < 8; i++) {
        float* crow = g_ctx + (size_t)(m0 + ty * 8 + i) * 512 + n0 + tx * 8;
        float4 r0, r1;
        r0.x = acc[i][0] + bb0.x; r0.y = acc[i][1] + bb0.y;
        r0.z = acc[i][2] + bb0.z; r0.w = acc[i][3] + bb0.w;
        r1.x = acc[i][4] + bb1.x; r1.y = acc[i][5] + bb1.y;
        r1.z = acc[i][6] + bb1.z; r1.w = acc[i][7] + bb1.w;
        *(float4*)crow = r0;
        *(float4*)(crow + 4) = r1;
    }
}

// ---------------- step: gates + LSTM pointwise (warp per (b,j)) --------------
__global__ __launch_bounds__(256) void k_gates(const float* __restrict__ Wih,
                                               const float* __restrict__ bih,
                                               const float* __restrict__ Whh,
                                               const float* __restrict__ bhh, int t) {
    int w = blockIdx.x * 8 + (threadIdx.x >> 5);
    int l = threadIdx.x & 31;
    int j = w & 511;
    int b = w >> 9;
    const float* xr = g_cat + ((size_t)b * Tq + t) * CATq + 1024;
    const float* hr = g_h + b * Hq;
    float4 xv0 = *(const float4*)(xr + 4 * l);
    float4 xv1 = *(const float4*)(xr + 4 * (l + 32));
    float4 hv0 = *(const float4*)(hr + 4 * l);
    float4 hv1 = *(const float4*)(hr + 4 * (l + 32));
    float4 hv2 = *(const float4*)(hr + 4 * (l + 64));
    float4 hv3 = *(const float4*)(hr + 4 * (l + 96));

    float s[4];
#pragma unroll
    for (int g = 0; g < 4; g++) {
        const float* wx = Wih + (size_t)(j + 512 * g) * Eq;
        const float* wh = Whh + (size_t)(j + 512 * g) * Hq;
        float acc = dot4(xv0, *(const float4*)(wx + 4 * l))
                  + dot4(xv1, *(const float4*)(wx + 4 * (l + 32)));
        acc += dot4(hv0, *(const float4*)(wh + 4 * l));
        acc += dot4(hv1, *(const float4*)(wh + 4 * (l + 32)));
        acc += dot4(hv2, *(const float4*)(wh + 4 * (l + 64)));
        acc += dot4(hv3, *(const float4*)(wh + 4 * (l + 96)));
        s[g] = acc;
    }
#pragma unroll
    for (int g = 0; g < 4; g++)
#pragma unroll
        for (int off = 16; off; off >>= 1)
            s[g] += __shfl_xor_sync(0xffffffffu, s[g], off);

    if (l == 0) {
        float ig = sigmoidf_(s[0] + bih[j] + bhh[j]);
        float fg = sigmoidf_(s[1] + bih[j + 512] + bhh[j + 512]);
        float gg = fast_tanh(s[2] + bih[j + 1024] + bhh[j + 1024]);
        float og = sigmoidf_(s[3] + bih[j + 1536] + bhh[j + 1536]);
        float cp = g_c[b * Hq + j];
        float ct = fg * cp + ig * gg;
        g_c[b * Hq + j]     = ct;
        g_hlstm[b * Hq + j] = og * fast_tanh(ct);
    }
}

// ---------------- step: inp = h_lstm @ W_in^T + b_in (warp per (b,h)) --------
__global__ __launch_bounds__(256) void k_inp(const float* __restrict__ Win,
                                             const float* __restrict__ bin) {
    int w = blockIdx.x * 8 + (threadIdx.x >> 5);
    int l = threadIdx.x & 31;
    int h = w & 511;
    int b = w >> 9;
    const float* hl = g_hlstm + b * Hq;
    const float* wr = Win + (size_t)h * Hq;
    float s = 0.f;
#pragma unroll
    for (int i = 0; i < 4; i++) {
        float4 hv = *(const float4*)(hl + 4 * (l + 32 * i));
        float4 wv = *(const float4*)(wr + 4 * (l + 32 * i));
        s += dot4(hv, wv);
    }
#pragma unroll
    for (int off = 16; off; off >>= 1)
        s += __shfl_xor_sync(0xffffffffu, s, off);
    if (l == 0) g_inp[b * Hq + h] = s + bin[h];
}

// ---------------- step: fused attention (warp = 32 s-rows, online softmax) ---
__global__ __launch_bounds__(256) void k_attn(const float* __restrict__ V) {
    int b = blockIdx.y;
    int p = blockIdx.x * 8 + (threadIdx.x >> 5);
    int l = threadIdx.x & 31;

    float4 v0 = *(const float4*)(V + 4 * l);
    float4 v1 = *(const float4*)(V + 128 + 4 * l);
    float4 v2 = *(const float4*)(V + 256 + 4 * l);
    float4 v3 = *(const float4*)(V + 384 + 4 * l);
    const float* ip = g_inp + b * Hq;
    float4 i0 = *(const float4*)(ip + 4 * l);
    float4 i1 = *(const float4*)(ip + 128 + 4 * l);
    float4 i2 = *(const float4*)(ip + 256 + 4 * l);
    float4 i3 = *(const float4*)(ip + 384 + 4 * l);

    float4 w0 = {0,0,0,0}, w1 = {0,0,0,0}, w2 = {0,0,0,0}, w3 = {0,0,0,0};
    float m = -1e30f, Z = 0.f;

    const float* base = g_ctx + ((size_t)b * Sq + (size_t)p * 32) * Hq;
    float4 c0 = *(const float4*)(base + 4 * l);
    float4 c1 = *(const float4*)(base + 128 + 4 * l);
    float4 c2 = *(const float4*)(base + 256 + 4 * l);
    float4 c3 = *(const float4*)(base + 384 + 4 * l);

    for (int s = 0; s < 32; ++s) {
        float4 n0, n1, n2, n3;
        if (s < 31) {
            const float* nb = base + (size_t)(s + 1) * Hq;
            n0 = *(const float4*)(nb + 4 * l);
            n1 = *(const float4*)(nb + 128 + 4 * l);
            n2 = *(const float4*)(nb + 256 + 4 * l);
            n3 = *(const float4*)(nb + 384 + 4 * l);
        }
        float part;
        part  = v0.x * tanh_hw(i0.x + c0.x);
        part += v0.y * tanh_hw(i0.y + c0.y);
        part += v0.z * tanh_hw(i0.z + c0.z);
        part += v0.w * tanh_hw(i0.w + c0.w);
        part += v1.x * tanh_hw(i1.x + c1.x);
        part += v1.y * tanh_hw(i1.y + c1.y);
        part += v1.z * tanh_hw(i1.z + c1.z);
        part += v1.w * tanh_hw(i1.w + c1.w);
        part += v2.x * tanh_hw(i2.x + c2.x);
        part += v2.y * tanh_hw(i2.y + c2.y);
        part += v2.z * tanh_hw(i2.z + c2.z);
        part += v2.w * tanh_hw(i2.w + c2.w);
        part += v3.x * tanh_hw(i3.x + c3.x);
        part += v3.y * tanh_hw(i3.y + c3.y);
        part += v3.z * tanh_hw(i3.z + c3.z);
        part += v3.w * tanh_hw(i3.w + c3.w);
#pragma unroll
        for (int off = 16; off; off >>= 1)
            part += __shfl_xor_sync(0xffffffffu, part, off);

        float nm   = fmaxf(m, part);
        float corr = __expf(m - nm);
        float pe   = __expf(part - nm);
        Z = Z * corr + pe;
        w0.x = w0.x * corr + pe * c0.x; w0.y = w0.y * corr + pe * c0.y;
        w0.z = w0.z * corr + pe * c0.z; w0.w = w0.w * corr + pe * c0.w;
        w1.x = w1.x * corr + pe * c1.x; w1.y = w1.y * corr + pe * c1.y;
        w1.z = w1.z * corr + pe * c1.z; w1.w = w1.w * corr + pe * c1.w;
        w2.x = w2.x * corr + pe * c2.x; w2.y = w2.y * corr + pe * c2.y;
        w2.z = w2.z * corr + pe * c2.z; w2.w = w2.w * corr + pe * c2.w;
        w3.x = w3.x * corr + pe * c3.x; w3.y = w3.y * corr + pe * c3.y;
        w3.z = w3.z * corr + pe * c3.z; w3.w = w3.w * corr + pe * c3.w;
        m = nm;
        c0 = n0; c1 = n1; c2 = n2; c3 = n3;
    }
    float* pp = g_part + ((size_t)b * NPq + p) * PSTRIDE;
    if (l == 0) { pp[0] = m; pp[1] = Z; }
    *(float4*)(pp + 4 + 4 * l)       = w0;
    *(float4*)(pp + 4 + 128 + 4 * l) = w1;
    *(float4*)(pp + 4 + 256 + 4 * l) = w2;
    *(float4*)(pp + 4 + 384 + 4 * l) = w3;
}

// ---------------- step: softmax partial combine -> weighted ------------------
__global__ __launch_bounds__(512) void k_wcomb(int t) {
    int b = blockIdx.x;
    int h = threadIdx.x;
    __shared__ float sm[NPq], se[NPq], sz[NPq];
    if (h < NPq) {
        const float* pp = g_part + ((size_t)b * NPq + h) * PSTRIDE;
        sm[h] = pp[0]; sz[h] = pp[1];
    }
    __syncthreads();
    float M = -1e30f;
#pragma unroll
    for (int p = 0; p < NPq; p++) M = fmaxf(M, sm[p]);
    if (h < NPq) se[h] = __expf(sm[h] - M);
    __syncthreads();
    float Zt = 0.f, wnum = 0.f;
#pragma unroll 8
    for (int p = 0; p < NPq; p++) {
        float e = se[p];
        Zt   += e * sz[p];
        wnum += e * g_part[((size_t)b * NPq + p) * PSTRIDE + 4 + h];
    }
    g_cat[((size_t)b * Tq + t) * CATq + 512 + h] = wnum / Zt;
}

// ---------------- step: h_t = tanh([weighted,h_lstm] @ W_ho^T + b_ho) --------
__global__ __launch_bounds__(256) void k_ht(const float* __restrict__ Who,
                                            const float* __restrict__ bho,
                                            int t, float* __restrict__ out_hf) {
    int w = blockIdx.x * 8 + (threadIdx.x >> 5);
    int l = threadIdx.x & 31;
    int h = w & 511;
    int b = w >> 9;
    const float* wr = Who + (size_t)h * 1024;
    float* catrow = g_cat + ((size_t)b * Tq + t) * CATq;
    const float* cw = catrow + 512;
    const float* hl = g_hlstm + b * Hq;
    float s = 0.f;
#pragma unroll
    for (int i = 0; i < 4; i++) {
        float4 wv = *(const float4*)(wr + 4 * (l + 32 * i));
        float4 xv = *(const float4*)(cw + 4 * (l + 32 * i));
        s += dot4(wv, xv);
    }
#pragma unroll
    for (int i = 0; i < 4; i++) {
        float4 wv = *(const float4*)(wr + 512 + 4 * (l + 32 * i));
        float4 xv = *(const float4*)(hl + 4 * (l + 32 * i));
        s += dot4(wv, xv);
    }
#pragma unroll
    for (int off = 16; off; off >>= 1)
        s += __shfl_xor_sync(0xffffffffu, s, off);
    if (l == 0) {
        float ht = fast_tanh(s + bho[h]);
        g_h[b * Hq + h] = ht;
        catrow[h] = ht;
        if (t == Tq - 1) out_hf[b * Hq + h] = ht;
    }
}

// ---------------- epilogue SGEMM: logits = cat @ W_out^T + b_out -------------
__global__ void k_sgemm_out(const float* __restrict__ Wout, const float* __restrict__ bout,
                            float* __restrict__ C) {
    __shared__ float As[16][128];
    __shared__ float Ws[16][64];
    const int tid  = threadIdx.x;
    const int m0   = blockIdx.x * 128;
    const int n0   = blockIdx.y * 64;
    const int arow = tid >> 1;
    const int acol = (tid & 1) * 8;
    const int brow = tid >> 2;
    const int bcol = (tid & 3) * 4;
    const int ty   = tid >> 4;
    const int tx   = tid & 15;

    float acc[8][4];
#pragma unroll
    for (int i = 0; i < 8; i++)
#pragma unroll
        for (int j = 0; j < 4; j++) acc[i][j] = 0.f;

    const bool wok = (n0 + brow) < NLq;
    for (int k0 = 0; k0 < CATq; k0 += 16) {
        float4 a0 = *(const float4*)(g_cat + (size_t)(m0 + arow) * CATq + k0 + acol);
        float4 a1 = *(const float4*)(g_cat + (size_t)(m0 + arow) * CATq + k0 + acol + 4);
        float4 bv = {0, 0, 0, 0};
        if (wok) bv = *(const float4*)(Wout + (size_t)(n0 + brow) * CATq + k0 + bcol);
        __syncthreads();
        As[acol + 0][arow] = a0.x; As[acol + 1][arow] = a0.y;
        As[acol + 2][arow] = a0.z; As[acol + 3][arow] = a0.w;
        As[acol + 4][arow] = a1.x; As[acol + 5][arow] = a1.y;
        As[acol + 6][arow] = a1.z; As[acol + 7][arow] = a1.w;
        Ws[bcol + 0][brow] = bv.x; Ws[bcol + 1][brow] = bv.y;
        Ws[bcol + 2][brow] = bv.z; Ws[bcol + 3][brow] = bv.w;
        __syncthreads();
#pragma unroll
        for (int k = 0; k < 16; k++) {
            float4 b4  = *(const float4*)&Ws[k][tx * 4];
            float4 ar0 = *(const float4*)&As[k][ty * 8];
            float4 ar1 = *(const float4*)&As[k][ty * 8 + 4];
            float ar[8] = {ar0.x, ar0.y, ar0.z, ar0.w, ar1.x, ar1.y, ar1.z, ar1.w};
#pragma unroll
            for (int i = 0; i < 8; i++) {
                acc[i][0] += ar[i] * b4.x;
                acc[i][1] += ar[i] * b4.y;
                acc[i][2] += ar[i] * b4.z;
                acc[i][3] += ar[i] * b4.w;
            }
        }
    }
#pragma unroll
    for (int i = 0; i < 8; i++) {
#pragma unroll
        for (int j = 0; j < 4; j++) {
            int n = n0 + tx * 4 + j;
            if (n < NLq)
                C[(size_t)(m0 + ty * 8 + i) * NLq + n] = acc[i][j] + bout[n];
        }
    }
}

// ---------------- epilogue: argmax ------------------------------------------
__global__ void k_argmax(const float* __restrict__ logits, float* __restrict__ preds) {
    int r = blockIdx.x * (blockDim.x >> 5) + (threadIdx.x >> 5);
    int lane = threadIdx.x & 31;
    const float* row = logits + (size_t)r * NLq;
    float bv = -1e30f; int bi = 0;
    for (int i = lane; i < NLq; i += 32) {
        float v = row[i];
        if (v > bv) { bv = v; bi = i; }
    }
#pragma unroll
    for (int off = 16; off; off >>= 1) {
        float ov = __shfl_xor_sync(0xffffffffu, bv, off);
        int   oi = __shfl_xor_sync(0xffffffffu, bi, off);
        if (ov > bv || (ov == bv && oi < bi)) { bv = ov; bi = oi; }
    }
    if (lane == 0) preds[r] = (float)bi;
}

__global__ void k_copy_cf(float* __restrict__ out_cf) {
    int i = blockIdx.x * blockDim.x + threadIdx.x;
    if (i < Bq * Hq) out_cf[i] = g_c[i];
}

// ---------------- launch -----------------------------------------------------
extern "C" void kernel_launch(void* const* d_in, const int* in_sizes, int n_in,
                              void* d_out, int out_size) {
    const float* dec_in  = (const float*)d_in[2];
    const float* h0      = (const float*)d_in[3];
    const float* c0      = (const float*)d_in[4];
    const float* context = (const float*)d_in[5];
    const int*   labels  = (const int*)d_in[6];
    const float* lemb    = (const float*)d_in[7];
    const float* Wih     = (const float*)d_in[8];
    const float* bih     = (const float*)d_in[9];
    const float* Whh     = (const float*)d_in[10];
    const float* bhh     = (const float*)d_in[11];
    const float* Win     = (const float*)d_in[12];
    const float* bin     = (const float*)d_in[13];
    const float* Wctx    = (const float*)d_in[14];
    const float* bctx    = (const float*)d_in[15];
    const float* V       = (const float*)d_in[16];
    const float* Who     = (const float*)d_in[17];
    const float* bho     = (const float*)d_in[18];
    const float* Wout    = (const float*)d_in[19];
    const float* bout    = (const float*)d_in[20];

    float* out      = (float*)d_out;
    float* o_logits = out;
    float* o_preds  = out + (size_t)Bq * Tq * NLq;
    float* o_hf     = o_preds + Bq * Tq;
    float* o_cf     = o_hf + Bq * Hq;

    k_init<<<256, 256>>>(h0, c0, dec_in, labels, lemb);
    k_sgemm_ctx<<<dim3(512, 4), 256>>>(context, Wctx, bctx);

    for (int t = 0; t < Tq; ++t) {
        k_gates<<<2048, 256>>>(Wih, bih, Whh, bhh, t);
        k_inp<<<2048, 256>>>(Win, bin);
        k_attn<<<dim3(8, Bq), 256>>>(V);
        k_wcomb<<<Bq, 512>>>(t);
        k_ht<<<2048, 256>>>(Who, bho, t, o_hf);
    }

    k_sgemm_out<<<dim3(8, 32), 256>>>(Wout, bout, o_logits);
    k_argmax<<<128, 256>>>(o_logits, o_preds);
    k_copy_cf<<<64, 256>>>(o_cf);
}

// round 3
// speedup vs baseline: 3.1160x; 1.0026x over previous
#include <cuda_runtime.h>
#include <math.h>
#include <stddef.h>

// Problem constants
#define Bq   32
#define Sq   2048
#define Hq   512
#define Eq   256
#define Tq   32
#define NLq  2000
#define CATq 1280           // [h_t(512), weighted(512), x(256)]
#define NPq  64             // attention partials per batch row
#define PSTRIDE 516         // per-partial: m, Z, pad, pad, w[512]

// ---------------- scratch ----------------------------------------------------
__device__ float g_ctx[(size_t)Bq * Sq * Hq];   // 128 MB projected context
__device__ float g_h[Bq * Hq];
__device__ float g_c[Bq * Hq];
__device__ float g_hlstm[Bq * Hq];
__device__ float g_inp[Bq * Hq];
__device__ float g_part[(size_t)Bq * NPq * PSTRIDE];
__device__ float g_cat[(size_t)Bq * Tq * CATq];

// ---------------- math -------------------------------------------------------
__device__ __forceinline__ float fast_tanh(float x) {     // accurate (~1e-7)
    x = fminf(fmaxf(x, -15.f), 15.f);
    float e = __expf(2.f * x);
    return __fdividef(e - 1.f, e + 1.f);
}
__device__ __forceinline__ float tanh_hw(float x) {       // MUFU.TANH (~1e-5)
    float y;
    asm("tanh.approx.f32 %0, %1;" : "=f"(y) : "f"(x));
    return y;
}
__device__ __forceinline__ float sigmoidf_(float x) {
    return __fdividef(1.f, 1.f + __expf(-x));
}
__device__ __forceinline__ float dot4(float4 a, float4 b) {
    return a.x * b.x + a.y * b.y + a.z * b.z + a.w * b.w;
}

// ---------------- init -------------------------------------------------------
__global__ void k_init(const float* __restrict__ h0, const float* __restrict__ c0,
                       const float* __restrict__ dec_in, const int* __restrict__ labels,
                       const float* __restrict__ lemb) {
    int i = blockIdx.x * blockDim.x + threadIdx.x;
    if (i < Bq * Hq) { g_h[i] = h0[i]; g_c[i] = c0[i]; }
    int stride = gridDim.x * blockDim.x;
    for (int j = i; j < Bq * Tq * Eq; j += stride) {
        int e = j % Eq;
        int t = (j / Eq) % Tq;
        int b = j / (Eq * Tq);
        float v;
        if (t == 0) v = dec_in[b * Eq + e];
        else {
            int lab = labels[b * Tq + (t - 1)];
            v = lemb[(size_t)lab * Eq + e];
        }
        g_cat[((size_t)b * Tq + t) * CATq + 1024 + e] = v;
    }
}

// ---------------- prologue SGEMM: ctx = context @ W_ctx^T + b_ctx ------------
// M=65536, N=512, K=512. BM=BN=128, BK=8, 256 thr, 8x8/thread, double buffer.
__global__ __launch_bounds__(256) void k_sgemm_ctx(const float* __restrict__ A,
                                                   const float* __restrict__ W,
                                                   const float* __restrict__ bias) {
    __shared__ float As[2][8][128];
    __shared__ float Ws[2][8][128];
    const int tid = threadIdx.x;
    const int m0  = blockIdx.x * 128;
    const int n0  = blockIdx.y * 128;
    const int lr  = tid >> 1;
    const int lc  = (tid & 1) * 4;
    const int ty  = tid >> 4;
    const int tx  = tid & 15;

    float acc[8][8];
#pragma unroll
    for (int i = 0; i < 8; i++)
#pragma unroll
        for (int j = 0; j < 8; j++) acc[i][j] = 0.f;

    float4 a = *(const float4*)(A + (size_t)(m0 + lr) * 512 + lc);
    float4 w = *(const float4*)(W + (size_t)(n0 + lr) * 512 + lc);
    As[0][lc + 0][lr] = a.x; As[0][lc + 1][lr] = a.y;
    As[0][lc + 2][lr] = a.z; As[0][lc + 3][lr] = a.w;
    Ws[0][lc + 0][lr] = w.x; Ws[0][lc + 1][lr] = w.y;
    Ws[0][lc + 2][lr] = w.z; Ws[0][lc + 3][lr] = w.w;
    __syncthreads();

    int buf = 0;
    for (int k0 = 8; k0 <= 512; k0 += 8) {
        if (k0 < 512) {
            a = *(const float4*)(A + (size_t)(m0 + lr) * 512 + k0 + lc);
            w = *(const float4*)(W + (size_t)(n0 + lr) * 512 + k0 + lc);
        }
#pragma unroll
        for (int k = 0; k < 8; k++) {
            float4 a0 = *(const float4*)&As[buf][k][ty * 8];
            float4 a1 = *(const float4*)&As[buf][k][ty * 8 + 4];
            float4 b0 = *(const float4*)&Ws[buf][k][tx * 8];
            float4 b1 = *(const float4*)&Ws[buf][k][tx * 8 + 4];
            float ar[8] = {a0.x, a0.y, a0.z, a0.w, a1.x, a1.y, a1.z, a1.w};
            float br[8] = {b0.x, b0.y, b0.z, b0.w, b1.x, b1.y, b1.z, b1.w};
#pragma unroll
            for (int i = 0; i < 8; i++)
#pragma unroll
                for (int j = 0; j < 8; j++) acc[i][j] += ar[i] * br[j];
        }
        if (k0 < 512) {
            buf ^= 1;
            As[buf][lc + 0][lr] = a.x; As[buf][lc + 1][lr] = a.y;
            As[buf][lc + 2][lr] = a.z; As[buf][lc + 3][lr] = a.w;
            Ws[buf][lc + 0][lr] = w.x; Ws[buf][lc + 1][lr] = w.y;
            Ws[buf][lc + 2][lr] = w.z; Ws[buf][lc + 3][lr] = w.w;
            __syncthreads();
        }
    }
    float4 bb0 = *(const float4*)(bias + n0 + tx * 8);
    float4 bb1 = *(const float4*)(bias + n0 + tx * 8 + 4);
#pragma unroll
    for (int i = 0; i < 8; i++) {
        float* crow = g_ctx + (size_t)(m0 + ty * 8 + i) * 512 + n0 + tx * 8;
        float4 r0, r1;
        r0.x = acc[i][0] + bb0.x; r0.y = acc[i][1] + bb0.y;
        r0.z = acc[i][2] + bb0.z; r0.w = acc[i][3] + bb0.w;
        r1.x = acc[i][4] + bb1.x; r1.y = acc[i][5] + bb1.y;
        r1.z = acc[i][6] + bb1.z; r1.w = acc[i][7] + bb1.w;
        *(float4*)crow = r0;
        *(float4*)(crow + 4) = r1;
    }
}

// ---------------- step: gates + LSTM pointwise (warp per (b,j)) --------------
__global__ __launch_bounds__(256) void k_gates(const float* __restrict__ Wih,
                                               const float* __restrict__ bih,
                                               const float* __restrict__ Whh,
                                               const float* __restrict__ bhh, int t) {
    int w = blockIdx.x * 8 + (threadIdx.x >> 5);
    int l = threadIdx.x & 31;
    int j = w & 511;
    int b = w >> 9;
    const float* xr = g_cat + ((size_t)b * Tq + t) * CATq + 1024;
    const float* hr = g_h + b * Hq;
    float4 xv0 = *(const float4*)(xr + 4 * l);
    float4 xv1 = *(const float4*)(xr + 4 * (l + 32));
    float4 hv0 = *(const float4*)(hr + 4 * l);
    float4 hv1 = *(const float4*)(hr + 4 * (l + 32));
    float4 hv2 = *(const float4*)(hr + 4 * (l + 64));
    float4 hv3 = *(const float4*)(hr + 4 * (l + 96));

    float s[4];
#pragma unroll
    for (int g = 0; g < 4; g++) {
        const float* wx = Wih + (size_t)(j + 512 * g) * Eq;
        const float* wh = Whh + (size_t)(j + 512 * g) * Hq;
        float acc = dot4(xv0, *(const float4*)(wx + 4 * l))
                  + dot4(xv1, *(const float4*)(wx + 4 * (l + 32)));
        acc += dot4(hv0, *(const float4*)(wh + 4 * l));
        acc += dot4(hv1, *(const float4*)(wh + 4 * (l + 32)));
        acc += dot4(hv2, *(const float4*)(wh + 4 * (l + 64)));
        acc += dot4(hv3, *(const float4*)(wh + 4 * (l + 96)));
        s[g] = acc;
    }
#pragma unroll
    for (int g = 0; g < 4; g++)
#pragma unroll
        for (int off = 16; off; off >>= 1)
            s[g] += __shfl_xor_sync(0xffffffffu, s[g], off);

    if (l == 0) {
        float ig = sigmoidf_(s[0] + bih[j] + bhh[j]);
        float fg = sigmoidf_(s[1] + bih[j + 512] + bhh[j + 512]);
        float gg = fast_tanh(s[2] + bih[j + 1024] + bhh[j + 1024]);
        float og = sigmoidf_(s[3] + bih[j + 1536] + bhh[j + 1536]);
        float cp = g_c[b * Hq + j];
        float ct = fg * cp + ig * gg;
        g_c[b * Hq + j]     = ct;
        g_hlstm[b * Hq + j] = og * fast_tanh(ct);
    }
}

// ---------------- step: inp = h_lstm @ W_in^T + b_in (warp per (b,h)) --------
__global__ __launch_bounds__(256) void k_inp(const float* __restrict__ Win,
                                             const float* __restrict__ bin) {
    int w = blockIdx.x * 8 + (threadIdx.x >> 5);
    int l = threadIdx.x & 31;
    int h = w & 511;
    int b = w >> 9;
    const float* hl = g_hlstm + b * Hq;
    const float* wr = Win + (size_t)h * Hq;
    float s = 0.f;
#pragma unroll
    for (int i = 0; i < 4; i++) {
        float4 hv = *(const float4*)(hl + 4 * (l + 32 * i));
        float4 wv = *(const float4*)(wr + 4 * (l + 32 * i));
        s += dot4(hv, wv);
    }
#pragma unroll
    for (int off = 16; off; off >>= 1)
        s += __shfl_xor_sync(0xffffffffu, s, off);
    if (l == 0) g_inp[b * Hq + h] = s + bin[h];
}

// ---------------- step: fused attention (warp = 32 s-rows, online softmax) ---
__global__ __launch_bounds__(256) void k_attn(const float* __restrict__ V) {
    int b = blockIdx.y;
    int p = blockIdx.x * 8 + (threadIdx.x >> 5);
    int l = threadIdx.x & 31;

    float4 v0 = *(const float4*)(V + 4 * l);
    float4 v1 = *(const float4*)(V + 128 + 4 * l);
    float4 v2 = *(const float4*)(V + 256 + 4 * l);
    float4 v3 = *(const float4*)(V + 384 + 4 * l);
    const float* ip = g_inp + b * Hq;
    float4 i0 = *(const float4*)(ip + 4 * l);
    float4 i1 = *(const float4*)(ip + 128 + 4 * l);
    float4 i2 = *(const float4*)(ip + 256 + 4 * l);
    float4 i3 = *(const float4*)(ip + 384 + 4 * l);

    float4 w0 = {0,0,0,0}, w1 = {0,0,0,0}, w2 = {0,0,0,0}, w3 = {0,0,0,0};
    float m = -1e30f, Z = 0.f;

    const float* base = g_ctx + ((size_t)b * Sq + (size_t)p * 32) * Hq;
    float4 c0 = *(const float4*)(base + 4 * l);
    float4 c1 = *(const float4*)(base + 128 + 4 * l);
    float4 c2 = *(const float4*)(base + 256 + 4 * l);
    float4 c3 = *(const float4*)(base + 384 + 4 * l);

    for (int s = 0; s < 32; ++s) {
        float4 n0, n1, n2, n3;
        if (s < 31) {
            const float* nb = base + (size_t)(s + 1) * Hq;
            n0 = *(const float4*)(nb + 4 * l);
            n1 = *(const float4*)(nb + 128 + 4 * l);
            n2 = *(const float4*)(nb + 256 + 4 * l);
            n3 = *(const float4*)(nb + 384 + 4 * l);
        }
        float part;
        part  = v0.x * tanh_hw(i0.x + c0.x);
        part += v0.y * tanh_hw(i0.y + c0.y);
        part += v0.z * tanh_hw(i0.z + c0.z);
        part += v0.w * tanh_hw(i0.w + c0.w);
        part += v1.x * tanh_hw(i1.x + c1.x);
        part += v1.y * tanh_hw(i1.y + c1.y);
        part += v1.z * tanh_hw(i1.z + c1.z);
        part += v1.w * tanh_hw(i1.w + c1.w);
        part += v2.x * tanh_hw(i2.x + c2.x);
        part += v2.y * tanh_hw(i2.y + c2.y);
        part += v2.z * tanh_hw(i2.z + c2.z);
        part += v2.w * tanh_hw(i2.w + c2.w);
        part += v3.x * tanh_hw(i3.x + c3.x);
        part += v3.y * tanh_hw(i3.y + c3.y);
        part += v3.z * tanh_hw(i3.z + c3.z);
        part += v3.w * tanh_hw(i3.w + c3.w);
#pragma unroll
        for (int off = 16; off; off >>= 1)
            part += __shfl_xor_sync(0xffffffffu, part, off);

        float nm   = fmaxf(m, part);
        float corr = __expf(m - nm);
        float pe   = __expf(part - nm);
        Z = Z * corr + pe;
        w0.x = w0.x * corr + pe * c0.x; w0.y = w0.y * corr + pe * c0.y;
        w0.z = w0.z * corr + pe * c0.z; w0.w = w0.w * corr + pe * c0.w;
        w1.x = w1.x * corr + pe * c1.x; w1.y = w1.y * corr + pe * c1.y;
        w1.z = w1.z * corr + pe * c1.z; w1.w = w1.w * corr + pe * c1.w;
        w2.x = w2.x * corr + pe * c2.x; w2.y = w2.y * corr + pe * c2.y;
        w2.z = w2.z * corr + pe * c2.z; w2.w = w2.w * corr + pe * c2.w;
        w3.x = w3.x * corr + pe * c3.x; w3.y = w3.y * corr + pe * c3.y;
        w3.z = w3.z * corr + pe * c3.z; w3.w = w3.w * corr + pe * c3.w;
        m = nm;
        c0 = n0; c1 = n1; c2 = n2; c3 = n3;
    }
    float* pp = g_part + ((size_t)b * NPq + p) * PSTRIDE;
    if (l == 0) { pp[0] = m; pp[1] = Z; }
    *(float4*)(pp + 4 + 4 * l)       = w0;
    *(float4*)(pp + 4 + 128 + 4 * l) = w1;
    *(float4*)(pp + 4 + 256 + 4 * l) = w2;
    *(float4*)(pp + 4 + 384 + 4 * l) = w3;
}

// ---------------- step: softmax partial combine -> weighted ------------------
__global__ __launch_bounds__(512) void k_wcomb(int t) {
    int b = blockIdx.x;
    int h = threadIdx.x;
    __shared__ float sm[NPq], se[NPq], sz[NPq];
    if (h < NPq) {
        const float* pp = g_part + ((size_t)b * NPq + h) * PSTRIDE;
        sm[h] = pp[0]; sz[h] = pp[1];
    }
    __syncthreads();
    float M = -1e30f;
#pragma unroll
    for (int p = 0; p < NPq; p++) M = fmaxf(M, sm[p]);
    if (h < NPq) se[h] = __expf(sm[h] - M);
    __syncthreads();
    float Zt = 0.f, wnum = 0.f;
#pragma unroll 8
    for (int p = 0; p < NPq; p++) {
        float e = se[p];
        Zt   += e * sz[p];
        wnum += e * g_part[((size_t)b * NPq + p) * PSTRIDE + 4 + h];
    }
    g_cat[((size_t)b * Tq + t) * CATq + 512 + h] = wnum / Zt;
}

// ---------------- step: h_t = tanh([weighted,h_lstm] @ W_ho^T + b_ho) --------
__global__ __launch_bounds__(256) void k_ht(const float* __restrict__ Who,
                                            const float* __restrict__ bho,
                                            int t, float* __restrict__ out_hf) {
    int w = blockIdx.x * 8 + (threadIdx.x >> 5);
    int l = threadIdx.x & 31;
    int h = w & 511;
    int b = w >> 9;
    const float* wr = Who + (size_t)h * 1024;
    float* catrow = g_cat + ((size_t)b * Tq + t) * CATq;
    const float* cw = catrow + 512;
    const float* hl = g_hlstm + b * Hq;
    float s = 0.f;
#pragma unroll
    for (int i = 0; i < 4; i++) {
        float4 wv = *(const float4*)(wr + 4 * (l + 32 * i));
        float4 xv = *(const float4*)(cw + 4 * (l + 32 * i));
        s += dot4(wv, xv);
    }
#pragma unroll
    for (int i = 0; i < 4; i++) {
        float4 wv = *(const float4*)(wr + 512 + 4 * (l + 32 * i));
        float4 xv = *(const float4*)(hl + 4 * (l + 32 * i));
        s += dot4(wv, xv);
    }
#pragma unroll
    for (int off = 16; off; off >>= 1)
        s += __shfl_xor_sync(0xffffffffu, s, off);
    if (l == 0) {
        float ht = fast_tanh(s + bho[h]);
        g_h[b * Hq + h] = ht;
        catrow[h] = ht;
        if (t == Tq - 1) out_hf[b * Hq + h] = ht;
    }
}

// ---------------- epilogue SGEMM: logits = cat @ W_out^T + b_out -------------
__global__ void k_sgemm_out(const float* __restrict__ Wout, const float* __restrict__ bout,
                            float* __restrict__ C) {
    __shared__ float As[16][128];
    __shared__ float Ws[16][64];
    const int tid  = threadIdx.x;
    const int m0   = blockIdx.x * 128;
    const int n0   = blockIdx.y * 64;
    const int arow = tid >> 1;
    const int acol = (tid & 1) * 8;
    const int brow = tid >> 2;
    const int bcol = (tid & 3) * 4;
    const int ty   = tid >> 4;
    const int tx   = tid & 15;

    float acc[8][4];
#pragma unroll
    for (int i = 0; i < 8; i++)
#pragma unroll
        for (int j = 0; j < 4; j++) acc[i][j] = 0.f;

    const bool wok = (n0 + brow) < NLq;
    for (int k0 = 0; k0 < CATq; k0 += 16) {
        float4 a0 = *(const float4*)(g_cat + (size_t)(m0 + arow) * CATq + k0 + acol);
        float4 a1 = *(const float4*)(g_cat + (size_t)(m0 + arow) * CATq + k0 + acol + 4);
        float4 bv = {0, 0, 0, 0};
        if (wok) bv = *(const float4*)(Wout + (size_t)(n0 + brow) * CATq + k0 + bcol);
        __syncthreads();
        As[acol + 0][arow] = a0.x; As[acol + 1][arow] = a0.y;
        As[acol + 2][arow] = a0.z; As[acol + 3][arow] = a0.w;
        As[acol + 4][arow] = a1.x; As[acol + 5][arow] = a1.y;
        As[acol + 6][arow] = a1.z; As[acol + 7][arow] = a1.w;
        Ws[bcol + 0][brow] = bv.x; Ws[bcol + 1][brow] = bv.y;
        Ws[bcol + 2][brow] = bv.z; Ws[bcol + 3][brow] = bv.w;
        __syncthreads();
#pragma unroll
        for (int k = 0; k < 16; k++) {
            float4 b4  = *(const float4*)&Ws[k][tx * 4];
            float4 ar0 = *(const float4*)&As[k][ty * 8];
            float4 ar1 = *(const float4*)&As[k][ty * 8 + 4];
            float ar[8] = {ar0.x, ar0.y, ar0.z, ar0.w, ar1.x, ar1.y, ar1.z, ar1.w};
#pragma unroll
            for (int i = 0; i < 8; i++) {
                acc[i][0] += ar[i] * b4.x;
                acc[i][1] += ar[i] * b4.y;
                acc[i][2] += ar[i] * b4.z;
                acc[i][3] += ar[i] * b4.w;
            }
        }
    }
#pragma unroll
    for (int i = 0; i < 8; i++) {
#pragma unroll
        for (int j = 0; j < 4; j++) {
            int n = n0 + tx * 4 + j;
            if (n < NLq)
                C[(size_t)(m0 + ty * 8 + i) * NLq + n] = acc[i][j] + bout[n];
        }
    }
}

// ---------------- epilogue: argmax ------------------------------------------
__global__ void k_argmax(const float* __restrict__ logits, float* __restrict__ preds) {
    int r = blockIdx.x * (blockDim.x >> 5) + (threadIdx.x >> 5);
    int lane = threadIdx.x & 31;
    const float* row = logits + (size_t)r * NLq;
    float bv = -1e30f; int bi = 0;
    for (int i = lane; i < NLq; i += 32) {
        float v = row[i];
        if (v > bv) { bv = v; bi = i; }
    }
#pragma unroll
    for (int off = 16; off; off >>= 1) {
        float ov = __shfl_xor_sync(0xffffffffu, bv, off);
        int   oi = __shfl_xor_sync(0xffffffffu, bi, off);
        if (ov > bv || (ov == bv && oi < bi)) { bv = ov; bi = oi; }
    }
    if (lane == 0) preds[r] = (float)bi;
}

__global__ void k_copy_cf(float* __restrict__ out_cf) {
    int i = blockIdx.x * blockDim.x + threadIdx.x;
    if (i < Bq * Hq) out_cf[i] = g_c[i];
}

// ---------------- launch -----------------------------------------------------
extern "C" void kernel_launch(void* const* d_in, const int* in_sizes, int n_in,
                              void* d_out, int out_size) {
    const float* dec_in  = (const float*)d_in[2];
    const float* h0      = (const float*)d_in[3];
    const float* c0      = (const float*)d_in[4];
    const float* context = (const float*)d_in[5];
    const int*   labels  = (const int*)d_in[6];
    const float* lemb    = (const float*)d_in[7];
    const float* Wih     = (const float*)d_in[8];
    const float* bih     = (const float*)d_in[9];
    const float* Whh     = (const float*)d_in[10];
    const float* bhh     = (const float*)d_in[11];
    const float* Win     = (const float*)d_in[12];
    const float* bin     = (const float*)d_in[13];
    const float* Wctx    = (const float*)d_in[14];
    const float* bctx    = (const float*)d_in[15];
    const float* V       = (const float*)d_in[16];
    const float* Who     = (const float*)d_in[17];
    const float* bho     = (const float*)d_in[18];
    const float* Wout    = (const float*)d_in[19];
    const float* bout    = (const float*)d_in[20];

    float* out      = (float*)d_out;
    float* o_logits = out;
    float* o_preds  = out + (size_t)Bq * Tq * NLq;
    float* o_hf     = o_preds + Bq * Tq;
    float* o_cf     = o_hf + Bq * Hq;

    k_init<<<256, 256>>>(h0, c0, dec_in, labels, lemb);
    k_sgemm_ctx<<<dim3(512, 4), 256>>>(context, Wctx, bctx);

    for (int t = 0; t < Tq; ++t) {
        k_gates<<<2048, 256>>>(Wih, bih, Whh, bhh, t);
        k_inp<<<2048, 256>>>(Win, bin);
        k_attn<<<dim3(8, Bq), 256>>>(V);
        k_wcomb<<<Bq, 512>>>(t);
        k_ht<<<2048, 256>>>(Who, bho, t, o_hf);
    }

    k_sgemm_out<<<dim3(8, 32), 256>>>(Wout, bout, o_logits);
    k_argmax<<<128, 256>>>(o_logits, o_preds);
    k_copy_cf<<<64, 256>>>(o_cf);
}

// round 4
// speedup vs baseline: 3.1164x; 1.0001x over previous
#include <cuda_runtime.h>
#include <math.h>
#include <stddef.h>

// Problem constants
#define Bq   32
#define Sq   2048
#define Hq   512
#define Eq   256
#define Tq   32
#define NLq  2000
#define CATq 1280           // [h_t(512), weighted(512), x(256)]
#define NPq  64             // attention partials per batch row
#define PSTRIDE 516         // per-partial: m, Z, pad, pad, w[512]

// ---------------- scratch ----------------------------------------------------
__device__ float g_ctx[(size_t)Bq * Sq * Hq];   // 128 MB projected context
__device__ float g_h[Bq * Hq];
__device__ float g_c[Bq * Hq];
__device__ float g_hlstm[Bq * Hq];
__device__ float g_inp[Bq * Hq];
__device__ float g_part[(size_t)Bq * NPq * PSTRIDE];
__device__ float g_cat[(size_t)Bq * Tq * CATq];

// ---------------- math -------------------------------------------------------
__device__ __forceinline__ float fast_tanh(float x) {     // accurate (~1e-7)
    x = fminf(fmaxf(x, -15.f), 15.f);
    float e = __expf(2.f * x);
    return __fdividef(e - 1.f, e + 1.f);
}
__device__ __forceinline__ float tanh_hw(float x) {       // MUFU.TANH (~1e-5)
    float y;
    asm("tanh.approx.f32 %0, %1;" : "=f"(y) : "f"(x));
    return y;
}
__device__ __forceinline__ float sigmoidf_(float x) {
    return __fdividef(1.f, 1.f + __expf(-x));
}
__device__ __forceinline__ float dot4(float4 a, float4 b) {
    return a.x * b.x + a.y * b.y + a.z * b.z + a.w * b.w;
}

// ---------------- init -------------------------------------------------------
__global__ void k_init(const float* __restrict__ h0, const float* __restrict__ c0,
                       const float* __restrict__ dec_in, const int* __restrict__ labels,
                       const float* __restrict__ lemb) {
    int i = blockIdx.x * blockDim.x + threadIdx.x;
    if (i < Bq * Hq) { g_h[i] = h0[i]; g_c[i] = c0[i]; }
    int stride = gridDim.x * blockDim.x;
    for (int j = i; j < Bq * Tq * Eq; j += stride) {
        int e = j % Eq;
        int t = (j / Eq) % Tq;
        int b = j / (Eq * Tq);
        float v;
        if (t == 0) v = dec_in[b * Eq + e];
        else {
            int lab = labels[b * Tq + (t - 1)];
            v = lemb[(size_t)lab * Eq + e];
        }
        g_cat[((size_t)b * Tq + t) * CATq + 1024 + e] = v;
    }
}

// ---------------- prologue SGEMM: ctx = context @ W_ctx^T + b_ctx ------------
// M=65536, N=512, K=512. BM=BN=128, BK=8, 256 thr, 8x8/thread, double buffer.
__global__ __launch_bounds__(256) void k_sgemm_ctx(const float* __restrict__ A,
                                                   const float* __restrict__ W,
                                                   const float* __restrict__ bias) {
    __shared__ float As[2][8][128];
    __shared__ float Ws[2][8][128];
    const int tid = threadIdx.x;
    const int m0  = blockIdx.x * 128;
    const int n0  = blockIdx.y * 128;
    const int lr  = tid >> 1;
    const int lc  = (tid & 1) * 4;
    const int ty  = tid >> 4;
    const int tx  = tid & 15;

    float acc[8][8];
#pragma unroll
    for (int i = 0; i < 8; i++)
#pragma unroll
        for (int j = 0; j < 8; j++) acc[i][j] = 0.f;

    float4 a = *(const float4*)(A + (size_t)(m0 + lr) * 512 + lc);
    float4 w = *(const float4*)(W + (size_t)(n0 + lr) * 512 + lc);
    As[0][lc + 0][lr] = a.x; As[0][lc + 1][lr] = a.y;
    As[0][lc + 2][lr] = a.z; As[0][lc + 3][lr] = a.w;
    Ws[0][lc + 0][lr] = w.x; Ws[0][lc + 1][lr] = w.y;
    Ws[0][lc + 2][lr] = w.z; Ws[0][lc + 3][lr] = w.w;
    __syncthreads();

    int buf = 0;
    for (int k0 = 8; k0 <= 512; k0 += 8) {
        if (k0 < 512) {
            a = *(const float4*)(A + (size_t)(m0 + lr) * 512 + k0 + lc);
            w = *(const float4*)(W + (size_t)(n0 + lr) * 512 + k0 + lc);
        }
#pragma unroll
        for (int k = 0; k < 8; k++) {
            float4 a0 = *(const float4*)&As[buf][k][ty * 8];
            float4 a1 = *(const float4*)&As[buf][k][ty * 8 + 4];
            float4 b0 = *(const float4*)&Ws[buf][k][tx * 8];
            float4 b1 = *(const float4*)&Ws[buf][k][tx * 8 + 4];
            float ar[8] = {a0.x, a0.y, a0.z, a0.w, a1.x, a1.y, a1.z, a1.w};
            float br[8] = {b0.x, b0.y, b0.z, b0.w, b1.x, b1.y, b1.z, b1.w};
#pragma unroll
            for (int i = 0; i < 8; i++)
#pragma unroll
                for (int j = 0; j < 8; j++) acc[i][j] += ar[i] * br[j];
        }
        if (k0 < 512) {
            buf ^= 1;
            As[buf][lc + 0][lr] = a.x; As[buf][lc + 1][lr] = a.y;
            As[buf][lc + 2][lr] = a.z; As[buf][lc + 3][lr] = a.w;
            Ws[buf][lc + 0][lr] = w.x; Ws[buf][lc + 1][lr] = w.y;
            Ws[buf][lc + 2][lr] = w.z; Ws[buf][lc + 3][lr] = w.w;
            __syncthreads();
        }
    }
    float4 bb0 = *(const float4*)(bias + n0 + tx * 8);
    float4 bb1 = *(const float4*)(bias + n0 + tx * 8 + 4);
#pragma unroll
    for (int i = 0; i < 8; i++) {
        float* crow = g_ctx + (size_t)(m0 + ty * 8 + i) * 512 + n0 + tx * 8;
        float4 r0, r1;
        r0.x = acc[i][0] + bb0.x; r0.y = acc[i][1] + bb0.y;
        r0.z = acc[i][2] + bb0.z; r0.w = acc[i][3] + bb0.w;
        r1.x = acc[i][4] + bb1.x; r1.y = acc[i][5] + bb1.y;
        r1.z = acc[i][6] + bb1.z; r1.w = acc[i][7] + bb1.w;
        *(float4*)crow = r0;
        *(float4*)(crow + 4) = r1;
    }
}

// ---------------- step: gates + LSTM pointwise (warp per (b,j)) --------------
__global__ __launch_bounds__(256) void k_gates(const float* __restrict__ Wih,
                                               const float* __restrict__ bih,
                                               const float* __restrict__ Whh,
                                               const float* __restrict__ bhh, int t) {
    int w = blockIdx.x * 8 + (threadIdx.x >> 5);
    int l = threadIdx.x & 31;
    int j = w & 511;
    int b = w >> 9;
    const float* xr = g_cat + ((size_t)b * Tq + t) * CATq + 1024;
    const float* hr = g_h + b * Hq;
    float4 xv0 = *(const float4*)(xr + 4 * l);
    float4 xv1 = *(const float4*)(xr + 4 * (l + 32));
    float4 hv0 = *(const float4*)(hr + 4 * l);
    float4 hv1 = *(const float4*)(hr + 4 * (l + 32));
    float4 hv2 = *(const float4*)(hr + 4 * (l + 64));
    float4 hv3 = *(const float4*)(hr + 4 * (l + 96));

    float s[4];
#pragma unroll
    for (int g = 0; g < 4; g++) {
        const float* wx = Wih + (size_t)(j + 512 * g) * Eq;
        const float* wh = Whh + (size_t)(j + 512 * g) * Hq;
        float acc = dot4(xv0, *(const float4*)(wx + 4 * l))
                  + dot4(xv1, *(const float4*)(wx + 4 * (l + 32)));
        acc += dot4(hv0, *(const float4*)(wh + 4 * l));
        acc += dot4(hv1, *(const float4*)(wh + 4 * (l + 32)));
        acc += dot4(hv2, *(const float4*)(wh + 4 * (l + 64)));
        acc += dot4(hv3, *(const float4*)(wh + 4 * (l + 96)));
        s[g] = acc;
    }
#pragma unroll
    for (int g = 0; g < 4; g++)
#pragma unroll
        for (int off = 16; off; off >>= 1)
            s[g] += __shfl_xor_sync(0xffffffffu, s[g], off);

    if (l == 0) {
        float ig = sigmoidf_(s[0] + bih[j] + bhh[j]);
        float fg = sigmoidf_(s[1] + bih[j + 512] + bhh[j + 512]);
        float gg = fast_tanh(s[2] + bih[j + 1024] + bhh[j + 1024]);
        float og = sigmoidf_(s[3] + bih[j + 1536] + bhh[j + 1536]);
        float cp = g_c[b * Hq + j];
        float ct = fg * cp + ig * gg;
        g_c[b * Hq + j]     = ct;
        g_hlstm[b * Hq + j] = og * fast_tanh(ct);
    }
}

// ---------------- step: inp = h_lstm @ W_in^T + b_in (warp per (b,h)) --------
__global__ __launch_bounds__(256) void k_inp(const float* __restrict__ Win,
                                             const float* __restrict__ bin) {
    int w = blockIdx.x * 8 + (threadIdx.x >> 5);
    int l = threadIdx.x & 31;
    int h = w & 511;
    int b = w >> 9;
    const float* hl = g_hlstm + b * Hq;
    const float* wr = Win + (size_t)h * Hq;
    float s = 0.f;
#pragma unroll
    for (int i = 0; i < 4; i++) {
        float4 hv = *(const float4*)(hl + 4 * (l + 32 * i));
        float4 wv = *(const float4*)(wr + 4 * (l + 32 * i));
        s += dot4(hv, wv);
    }
#pragma unroll
    for (int off = 16; off; off >>= 1)
        s += __shfl_xor_sync(0xffffffffu, s, off);
    if (l == 0) g_inp[b * Hq + h] = s + bin[h];
}

// ---------------- step: fused attention (warp = 32 s-rows, online softmax) ---
__global__ __launch_bounds__(256) void k_attn(const float* __restrict__ V) {
    int b = blockIdx.y;
    int p = blockIdx.x * 8 + (threadIdx.x >> 5);
    int l = threadIdx.x & 31;

    float4 v0 = *(const float4*)(V + 4 * l);
    float4 v1 = *(const float4*)(V + 128 + 4 * l);
    float4 v2 = *(const float4*)(V + 256 + 4 * l);
    float4 v3 = *(const float4*)(V + 384 + 4 * l);
    const float* ip = g_inp + b * Hq;
    float4 i0 = *(const float4*)(ip + 4 * l);
    float4 i1 = *(const float4*)(ip + 128 + 4 * l);
    float4 i2 = *(const float4*)(ip + 256 + 4 * l);
    float4 i3 = *(const float4*)(ip + 384 + 4 * l);

    float4 w0 = {0,0,0,0}, w1 = {0,0,0,0}, w2 = {0,0,0,0}, w3 = {0,0,0,0};
    float m = -1e30f, Z = 0.f;

    const float* base = g_ctx + ((size_t)b * Sq + (size_t)p * 32) * Hq;
    float4 c0 = *(const float4*)(base + 4 * l);
    float4 c1 = *(const float4*)(base + 128 + 4 * l);
    float4 c2 = *(const float4*)(base + 256 + 4 * l);
    float4 c3 = *(const float4*)(base + 384 + 4 * l);

    for (int s = 0; s < 32; ++s) {
        float4 n0, n1, n2, n3;
        if (s < 31) {
            const float* nb = base + (size_t)(s + 1) * Hq;
            n0 = *(const float4*)(nb + 4 * l);
            n1 = *(const float4*)(nb + 128 + 4 * l);
            n2 = *(const float4*)(nb + 256 + 4 * l);
            n3 = *(const float4*)(nb + 384 + 4 * l);
        }
        float part;
        part  = v0.x * tanh_hw(i0.x + c0.x);
        part += v0.y * tanh_hw(i0.y + c0.y);
        part += v0.z * tanh_hw(i0.z + c0.z);
        part += v0.w * tanh_hw(i0.w + c0.w);
        part += v1.x * tanh_hw(i1.x + c1.x);
        part += v1.y * tanh_hw(i1.y + c1.y);
        part += v1.z * tanh_hw(i1.z + c1.z);
        part += v1.w * tanh_hw(i1.w + c1.w);
        part += v2.x * tanh_hw(i2.x + c2.x);
        part += v2.y * tanh_hw(i2.y + c2.y);
        part += v2.z * tanh_hw(i2.z + c2.z);
        part += v2.w * tanh_hw(i2.w + c2.w);
        part += v3.x * tanh_hw(i3.x + c3.x);
        part += v3.y * tanh_hw(i3.y + c3.y);
        part += v3.z * tanh_hw(i3.z + c3.z);
        part += v3.w * tanh_hw(i3.w + c3.w);
#pragma unroll
        for (int off = 16; off; off >>= 1)
            part += __shfl_xor_sync(0xffffffffu, part, off);

        float nm   = fmaxf(m, part);
        float corr = __expf(m - nm);
        float pe   = __expf(part - nm);
        Z = Z * corr + pe;
        w0.x = w0.x * corr + pe * c0.x; w0.y = w0.y * corr + pe * c0.y;
        w0.z = w0.z * corr + pe * c0.z; w0.w = w0.w * corr + pe * c0.w;
        w1.x = w1.x * corr + pe * c1.x; w1.y = w1.y * corr + pe * c1.y;
        w1.z = w1.z * corr + pe * c1.z; w1.w = w1.w * corr + pe * c1.w;
        w2.x = w2.x * corr + pe * c2.x; w2.y = w2.y * corr + pe * c2.y;
        w2.z = w2.z * corr + pe * c2.z; w2.w = w2.w * corr + pe * c2.w;
        w3.x = w3.x * corr + pe * c3.x; w3.y = w3.y * corr + pe * c3.y;
        w3.z = w3.z * corr + pe * c3.z; w3.w = w3.w * corr + pe * c3.w;
        m = nm;
        c0 = n0; c1 = n1; c2 = n2; c3 = n3;
    }
    float* pp = g_part + ((size_t)b * NPq + p) * PSTRIDE;
    if (l == 0) { pp[0] = m; pp[1] = Z; }
    *(float4*)(pp + 4 + 4 * l)       = w0;
    *(float4*)(pp + 4 + 128 + 4 * l) = w1;
    *(float4*)(pp + 4 + 256 + 4 * l) = w2;
    *(float4*)(pp + 4 + 384 + 4 * l) = w3;
}

// ---------------- step: softmax partial combine -> weighted ------------------
__global__ __launch_bounds__(512) void k_wcomb(int t) {
    int b = blockIdx.x;
    int h = threadIdx.x;
    __shared__ float sm[NPq], se[NPq], sz[NPq];
    if (h < NPq) {
        const float* pp = g_part + ((size_t)b * NPq + h) * PSTRIDE;
        sm[h] = pp[0]; sz[h] = pp[1];
    }
    __syncthreads();
    float M = -1e30f;
#pragma unroll
    for (int p = 0; p < NPq; p++) M = fmaxf(M, sm[p]);
    if (h < NPq) se[h] = __expf(sm[h] - M);
    __syncthreads();
    float Zt = 0.f, wnum = 0.f;
#pragma unroll 8
    for (int p = 0; p < NPq; p++) {
        float e = se[p];
        Zt   += e * sz[p];
        wnum += e * g_part[((size_t)b * NPq + p) * PSTRIDE + 4 + h];
    }
    g_cat[((size_t)b * Tq + t) * CATq + 512 + h] = wnum / Zt;
}

// ---------------- step: h_t = tanh([weighted,h_lstm] @ W_ho^T + b_ho) --------
__global__ __launch_bounds__(256) void k_ht(const float* __restrict__ Who,
                                            const float* __restrict__ bho,
                                            int t, float* __restrict__ out_hf) {
    int w = blockIdx.x * 8 + (threadIdx.x >> 5);
    int l = threadIdx.x & 31;
    int h = w & 511;
    int b = w >> 9;
    const float* wr = Who + (size_t)h * 1024;
    float* catrow = g_cat + ((size_t)b * Tq + t) * CATq;
    const float* cw = catrow + 512;
    const float* hl = g_hlstm + b * Hq;
    float s = 0.f;
#pragma unroll
    for (int i = 0; i < 4; i++) {
        float4 wv = *(const float4*)(wr + 4 * (l + 32 * i));
        float4 xv = *(const float4*)(cw + 4 * (l + 32 * i));
        s += dot4(wv, xv);
    }
#pragma unroll
    for (int i = 0; i < 4; i++) {
        float4 wv = *(const float4*)(wr + 512 + 4 * (l + 32 * i));
        float4 xv = *(const float4*)(hl + 4 * (l + 32 * i));
        s += dot4(wv, xv);
    }
#pragma unroll
    for (int off = 16; off; off >>= 1)
        s += __shfl_xor_sync(0xffffffffu, s, off);
    if (l == 0) {
        float ht = fast_tanh(s + bho[h]);
        g_h[b * Hq + h] = ht;
        catrow[h] = ht;
        if (t == Tq - 1) out_hf[b * Hq + h] = ht;
    }
}

// ---------------- epilogue SGEMM: logits = cat @ W_out^T + b_out -------------
__global__ void k_sgemm_out(const float* __restrict__ Wout, const float* __restrict__ bout,
                            float* __restrict__ C) {
    __shared__ float As[16][128];
    __shared__ float Ws[16][64];
    const int tid  = threadIdx.x;
    const int m0   = blockIdx.x * 128;
    const int n0   = blockIdx.y * 64;
    const int arow = tid >> 1;
    const int acol = (tid & 1) * 8;
    const int brow = tid >> 2;
    const int bcol = (tid & 3) * 4;
    const int ty   = tid >> 4;
    const int tx   = tid & 15;

    float acc[8][4];
#pragma unroll
    for (int i = 0; i < 8; i++)
#pragma unroll
        for (int j = 0; j < 4; j++) acc[i][j] = 0.f;

    const bool wok = (n0 + brow) < NLq;
    for (int k0 = 0; k0 < CATq; k0 += 16) {
        float4 a0 = *(const float4*)(g_cat + (size_t)(m0 + arow) * CATq + k0 + acol);
        float4 a1 = *(const float4*)(g_cat + (size_t)(m0 + arow) * CATq + k0 + acol + 4);
        float4 bv = {0, 0, 0, 0};
        if (wok) bv = *(const float4*)(Wout + (size_t)(n0 + brow) * CATq + k0 + bcol);
        __syncthreads();
        As[acol + 0][arow] = a0.x; As[acol + 1][arow] = a0.y;
        As[acol + 2][arow] = a0.z; As[acol + 3][arow] = a0.w;
        As[acol + 4][arow] = a1.x; As[acol + 5][arow] = a1.y;
        As[acol + 6][arow] = a1.z; As[acol + 7][arow] = a1.w;
        Ws[bcol + 0][brow] = bv.x; Ws[bcol + 1][brow] = bv.y;
        Ws[bcol + 2][brow] = bv.z; Ws[bcol + 3][brow] = bv.w;
        __syncthreads();
#pragma unroll
        for (int k = 0; k < 16; k++) {
            float4 b4  = *(const float4*)&Ws[k][tx * 4];
            float4 ar0 = *(const float4*)&As[k][ty * 8];
            float4 ar1 = *(const float4*)&As[k][ty * 8 + 4];
            float ar[8] = {ar0.x, ar0.y, ar0.z, ar0.w, ar1.x, ar1.y, ar1.z, ar1.w};
#pragma unroll
            for (int i = 0; i < 8; i++) {
                acc[i][0] += ar[i] * b4.x;
                acc[i][1] += ar[i] * b4.y;
                acc[i][2] += ar[i] * b4.z;
                acc[i][3] += ar[i] * b4.w;
            }
        }
    }
#pragma unroll
    for (int i = 0; i < 8; i++) {
#pragma unroll
        for (int j = 0; j < 4; j++) {
            int n = n0 + tx * 4 + j;
            if (n < NLq)
                C[(size_t)(m0 + ty * 8 + i) * NLq + n] = acc[i][j] + bout[n];
        }
    }
}

// ---------------- epilogue: argmax ------------------------------------------
__global__ void k_argmax(const float* __restrict__ logits, float* __restrict__ preds) {
    int r = blockIdx.x * (blockDim.x >> 5) + (threadIdx.x >> 5);
    int lane = threadIdx.x & 31;
    const float* row = logits + (size_t)r * NLq;
    float bv = -1e30f; int bi = 0;
    for (int i = lane; i < NLq; i += 32) {
        float v = row[i];
        if (v > bv) { bv = v; bi = i; }
    }
#pragma unroll
    for (int off = 16; off; off >>= 1) {
        float ov = __shfl_xor_sync(0xffffffffu, bv, off);
        int   oi = __shfl_xor_sync(0xffffffffu, bi, off);
        if (ov > bv || (ov == bv && oi < bi)) { bv = ov; bi = oi; }
    }
    if (lane == 0) preds[r] = (float)bi;
}

__global__ void k_copy_cf(float* __restrict__ out_cf) {
    int i = blockIdx.x * blockDim.x + threadIdx.x;
    if (i < Bq * Hq) out_cf[i] = g_c[i];
}

// ---------------- launch -----------------------------------------------------
extern "C" void kernel_launch(void* const* d_in, const int* in_sizes, int n_in,
                              void* d_out, int out_size) {
    const float* dec_in  = (const float*)d_in[2];
    const float* h0      = (const float*)d_in[3];
    const float* c0      = (const float*)d_in[4];
    const float* context = (const float*)d_in[5];
    const int*   labels  = (const int*)d_in[6];
    const float* lemb    = (const float*)d_in[7];
    const float* Wih     = (const float*)d_in[8];
    const float* bih     = (const float*)d_in[9];
    const float* Whh     = (const float*)d_in[10];
    const float* bhh     = (const float*)d_in[11];
    const float* Win     = (const float*)d_in[12];
    const float* bin     = (const float*)d_in[13];
    const float* Wctx    = (const float*)d_in[14];
    const float* bctx    = (const float*)d_in[15];
    const float* V       = (const float*)d_in[16];
    const float* Who     = (const float*)d_in[17];
    const float* bho     = (const float*)d_in[18];
    const float* Wout    = (const float*)d_in[19];
    const float* bout    = (const float*)d_in[20];

    float* out      = (float*)d_out;
    float* o_logits = out;
    float* o_preds  = out + (size_t)Bq * Tq * NLq;
    float* o_hf     = o_preds + Bq * Tq;
    float* o_cf     = o_hf + Bq * Hq;

    k_init<<<256, 256>>>(h0, c0, dec_in, labels, lemb);
    k_sgemm_ctx<<<dim3(512, 4), 256>>>(context, Wctx, bctx);

    for (int t = 0; t < Tq; ++t) {
        k_gates<<<2048, 256>>>(Wih, bih, Whh, bhh, t);
        k_inp<<<2048, 256>>>(Win, bin);
        k_attn<<<dim3(8, Bq), 256>>>(V);
        k_wcomb<<<Bq, 512>>>(t);
        k_ht<<<2048, 256>>>(Who, bho, t, o_hf);
    }

    k_sgemm_out<<<dim3(8, 32), 256>>>(Wout, bout, o_logits);
    k_argmax<<<128, 256>>>(o_logits, o_preds);
    k_copy_cf<<<64, 256>>>(o_cf);
}